// round 15
// baseline (speedup 1.0000x reference)
#include <cuda_runtime.h>
#include <cstdint>

#define IN_DIM   1024
#define OUT_DIM  65536
#define BATCH    32
#define THREADS  64                  // 2 warps per CTA
#define N_CTA    64                  // cols per CTA (32 per warp)
#define NCTAS    (OUT_DIM / N_CTA)   // 1024
#define CHUNK_K  128                 // x chunk staged in smem
#define GITS     (IN_DIM / 8)        // 128 k8 iterations total

static __device__ __forceinline__ uint32_t f2tf(float v) {
    uint32_t r;
    asm("cvt.rna.tf32.f32 %0, %1;" : "=r"(r) : "f"(v));
    return r;
}

// D(16x8) += A(16x8) @ B(8x8), tf32, fp32 accum (sm_80+ shape, no arch suffix)
static __device__ __forceinline__ void mma_k8(float* c, const uint32_t* a,
                                              uint32_t b0, uint32_t b1) {
    asm volatile(
        "mma.sync.aligned.m16n8k8.row.col.f32.tf32.tf32.f32 "
        "{%0,%1,%2,%3}, {%4,%5,%6,%7}, {%8,%9}, {%0,%1,%2,%3};"
        : "+f"(c[0]), "+f"(c[1]), "+f"(c[2]), "+f"(c[3])
        : "r"(a[0]), "r"(a[1]), "r"(a[2]), "r"(a[3]), "r"(b0), "r"(b1));
}

__global__ __launch_bounds__(THREADS, 8)
void sparse_linear_mma(const float* __restrict__ x,
                       const float* __restrict__ mask,
                       const float* __restrict__ w,
                       const float* __restrict__ bias,
                       float* __restrict__ out)
{
    // xs: tf32-converted x chunk; pad 132 -> fragment bank = (4*gid+tig+c)%32,
    // all 32 lanes distinct => conflict-free LDS.32.
    __shared__ uint32_t xs[32][132];                 // 16.9 KB
    // ps: per-warp product slabs, 2 slots x 8 rows, row stride 40 words ->
    // bank = (8*row + col)%32: the (4 rows x 8 cols) fragment read is a
    // bank bijection => conflict-free. STS.128 phases also conflict-free.
    __shared__ uint32_t ps[2][2][8][40];             // 2.6 KB

    const int tid  = threadIdx.x;
    const int warp = tid >> 5;       // 0..1
    const int lane = tid & 31;
    const int gid  = lane >> 2;      // 0..7
    const int tig  = lane & 3;       // 0..3
    const int cb   = blockIdx.x * N_CTA + warp * 32;

    float acc[2][4][4];
#pragma unroll
    for (int mt = 0; mt < 2; mt++)
#pragma unroll
        for (int nt = 0; nt < 4; nt++)
#pragma unroll
            for (int r = 0; r < 4; r++) acc[mt][nt][r] = 0.f;

    const float* wp = w    + cb;
    const float* mp = mask + cb;

    // Per-lane slab mapping: two (row, quad) pairs per 8x32 slab.
    const int r0 = lane >> 3, q0 = lane & 7;             // idx = lane
    const int r1 = (lane + 32) >> 3, q1 = lane & 7;      // idx = lane + 32

    float4 wA[2], mA[2], wB[2], mB[2];

#define LOADB(GIT, WV, MV)                                                     \
    {                                                                          \
        const size_t o0 = (size_t)((GIT) * 8 + r0) * OUT_DIM + q0 * 4;         \
        const size_t o1 = (size_t)((GIT) * 8 + r1) * OUT_DIM + q1 * 4;         \
        (WV)[0] = __ldcs(reinterpret_cast<const float4*>(wp + o0));            \
        (WV)[1] = __ldcs(reinterpret_cast<const float4*>(wp + o1));            \
        (MV)[0] = __ldcs(reinterpret_cast<const float4*>(mp + o0));            \
        (MV)[1] = __ldcs(reinterpret_cast<const float4*>(mp + o1));            \
    }

#define STS_SLAB(WV, MV, SLOT)                                                 \
    {                                                                          \
        uint4 u0, u1;                                                          \
        u0.x = f2tf((WV)[0].x * (MV)[0].x);                                    \
        u0.y = f2tf((WV)[0].y * (MV)[0].y);                                    \
        u0.z = f2tf((WV)[0].z * (MV)[0].z);                                    \
        u0.w = f2tf((WV)[0].w * (MV)[0].w);                                    \
        u1.x = f2tf((WV)[1].x * (MV)[1].x);                                    \
        u1.y = f2tf((WV)[1].y * (MV)[1].y);                                    \
        u1.z = f2tf((WV)[1].z * (MV)[1].z);                                    \
        u1.w = f2tf((WV)[1].w * (MV)[1].w);                                    \
        *reinterpret_cast<uint4*>(&ps[warp][SLOT][r0][q0 * 4]) = u0;           \
        *reinterpret_cast<uint4*>(&ps[warp][SLOT][r1][q1 * 4]) = u1;           \
    }

#define COMP(SLOT, GIT)                                                        \
    {                                                                          \
        const int lc = ((GIT) & 15) * 8;                                       \
        uint32_t a[2][4];                                                      \
        _Pragma("unroll")                                                      \
        for (int mt = 0; mt < 2; mt++) {                                       \
            a[mt][0] = xs[mt * 16 + gid][lc + tig];                            \
            a[mt][1] = xs[mt * 16 + gid + 8][lc + tig];                        \
            a[mt][2] = xs[mt * 16 + gid][lc + tig + 4];                        \
            a[mt][3] = xs[mt * 16 + gid + 8][lc + tig + 4];                    \
        }                                                                      \
        _Pragma("unroll")                                                      \
        for (int nt = 0; nt < 4; nt++) {                                       \
            const int c = nt * 8 + gid;                                        \
            const uint32_t b0 = ps[warp][SLOT][tig][c];                        \
            const uint32_t b1 = ps[warp][SLOT][tig + 4][c];                    \
            mma_k8(acc[0][nt], a[0], b0, b1);                                  \
            mma_k8(acc[1][nt], a[1], b0, b1);                                  \
        }                                                                      \
    }

    LOADB(0, wA, mA);
    LOADB(1, wB, mB);

#pragma unroll 1
    for (int git = 0; git < GITS; git += 2) {
        if ((git & 15) == 0) {
            // Chunk boundary: (re)stage tf32(x) for chunk git/16.
            const int k0 = (git >> 4) * CHUNK_K;
            __syncthreads();
            for (int i = tid; i < 32 * 32; i += THREADS) {
                const int row = i >> 5, q4 = i & 31;
                const float4 v = *reinterpret_cast<const float4*>(
                    x + row * IN_DIM + k0 + q4 * 4);
                uint4 u;
                u.x = f2tf(v.x); u.y = f2tf(v.y);
                u.z = f2tf(v.z); u.w = f2tf(v.w);
                *reinterpret_cast<uint4*>(&xs[row][q4 * 4]) = u;
            }
            __syncthreads();
        }

        STS_SLAB(wA, mA, 0);
        if (git + 2 < GITS) LOADB(git + 2, wA, mA);
        __syncwarp();
        COMP(0, git);

        STS_SLAB(wB, mB, 1);
        if (git + 3 < GITS) LOADB(git + 3, wB, mB);
        __syncwarp();
        COMP(1, git + 1);
    }
#undef LOADB
#undef STS_SLAB
#undef COMP

    // Epilogue: C fragments straight to out (full K accumulated; no reduce).
#pragma unroll
    for (int mt = 0; mt < 2; mt++)
#pragma unroll
        for (int nt = 0; nt < 4; nt++) {
            const int col = cb + nt * 8 + 2 * tig;
            const float2 b2 = *reinterpret_cast<const float2*>(bias + col);
            const int row = mt * 16 + gid;
            *reinterpret_cast<float2*>(out + (size_t)row * OUT_DIM + col) =
                make_float2(acc[mt][nt][0] + b2.x, acc[mt][nt][1] + b2.y);
            *reinterpret_cast<float2*>(out + (size_t)(row + 8) * OUT_DIM + col) =
                make_float2(acc[mt][nt][2] + b2.x, acc[mt][nt][3] + b2.y);
        }
}

extern "C" void kernel_launch(void* const* d_in, const int* in_sizes, int n_in,
                              void* d_out, int out_size) {
    const float* x    = (const float*)d_in[0];
    const float* mask = (const float*)d_in[1];
    const float* w    = (const float*)d_in[2];
    const float* bias = (const float*)d_in[3];
    float* out = (float*)d_out;

    sparse_linear_mma<<<NCTAS, THREADS>>>(x, mask, w, bias, out);
}